// round 2
// baseline (speedup 1.0000x reference)
#include <cuda_runtime.h>
#include <math.h>

#define NNODES 50000
#define NEDGES 1200000

// ---------------- scratch (device globals: no allocation allowed) ----------------
__device__ float g_in8[NNODES * 8];
__device__ float g_t1[NNODES * 128];
__device__ float g_t2[NNODES * 128];
__device__ float g_h[NNODES * 64];     // current node features
__device__ float g_D[NNODES * 128];    // [Af | As] dst-side projections (bias folded)
__device__ float g_S[NNODES * 128];    // [Bf | Bs] src-side projections
__device__ float g_acc[NNODES * 64];   // message accumulator
__device__ float g_t3[NNODES * 64];    // readout hidden

// ---------------- concat [x|forces_stack|forces_norm] -> [N,8] ----------------
__global__ void concat_kernel(const float* __restrict__ x, const float* __restrict__ fs,
                              const float* __restrict__ fn, float* __restrict__ out, int n) {
    int i = blockIdx.x * blockDim.x + threadIdx.x;
    if (i >= n) return;
    float4 xv = *reinterpret_cast<const float4*>(&x[i * 4]);
    out[i * 8 + 0] = xv.x;
    out[i * 8 + 1] = xv.y;
    out[i * 8 + 2] = xv.z;
    out[i * 8 + 3] = xv.w;
    out[i * 8 + 4] = fs[i * 3 + 0];
    out[i * 8 + 5] = fs[i * 3 + 1];
    out[i * 8 + 6] = fs[i * 3 + 2];
    out[i * 8 + 7] = fn[i];
}

// ---------------- generic node GEMM: out[n][ocol+j] = act(bias[j] + sum_k in[n][k]*W[k][j]) ----
// W row-major with row stride J. Weights tiled through smem; 32-node register blocking.
template <int K, int J, int KT, int NB, int ACT>
__global__ void __launch_bounds__(J) gemm_nodes_kernel(const float* __restrict__ in,
                                                       const float* __restrict__ W,
                                                       const float* __restrict__ bias,
                                                       float* __restrict__ out, int nN,
                                                       int ostride, int ocol) {
    __shared__ float sIn[NB][K];
    __shared__ float sW[KT][J];
    int j = threadIdx.x;
    int nb = blockIdx.x * NB;

    for (int idx = j; idx < NB * K; idx += J) {
        int n = idx / K, k = idx - n * K;
        int gn = nb + n;
        sIn[n][k] = (gn < nN) ? in[gn * K + k] : 0.0f;
    }
    float bv = bias ? __ldg(&bias[j]) : 0.0f;
    float acc[NB];
#pragma unroll
    for (int n = 0; n < NB; n++) acc[n] = bv;

    for (int k0 = 0; k0 < K; k0 += KT) {
        __syncthreads();
#pragma unroll 4
        for (int r = 0; r < KT; ++r) sW[r][j] = W[(k0 + r) * J + j];
        __syncthreads();
        for (int k = 0; k < KT; k += 4) {
            float w0 = sW[k][j], w1 = sW[k + 1][j], w2 = sW[k + 2][j], w3 = sW[k + 3][j];
#pragma unroll
            for (int n = 0; n < NB; ++n) {
                float4 v = *reinterpret_cast<const float4*>(&sIn[n][k0 + k]);
                float a = acc[n];
                a = fmaf(v.x, w0, a);
                a = fmaf(v.y, w1, a);
                a = fmaf(v.z, w2, a);
                a = fmaf(v.w, w3, a);
                acc[n] = a;
            }
        }
    }
#pragma unroll
    for (int n = 0; n < NB; n++) {
        int gn = nb + n;
        if (gn < nN) {
            float v = acc[n];
            if (ACT == 1) v = v > 0.0f ? v : 0.01f * v;       // leaky
            else if (ACT == 2) v = fmaxf(v, 0.0f);            // relu
            out[gn * ostride + ocol + j] = v;
        }
    }
}

// ---------------- zero accumulator ----------------
__global__ void zero_kernel(float* __restrict__ p, int n4) {
    int i = blockIdx.x * blockDim.x + threadIdx.x;
    if (i < n4) reinterpret_cast<float4*>(p)[i] = make_float4(0.f, 0.f, 0.f, 0.f);
}

// ---------------- edge kernel: one warp per edge; lane handles 2 cols ----------------
// m = sigmoid(Af[dst]+Bf[src]+Ef(d)) * softplus(As[dst]+Bs[src]+Es(d)); acc[dst] += m
// Ef/Es computed from the 9 non-negligible gaussian basis terms (window +-4; dropped <= e^-20).
__global__ void __launch_bounds__(256) edge_kernel(const int* __restrict__ src,
                                                   const int* __restrict__ dst,
                                                   const float* __restrict__ elen,
                                                   const float* __restrict__ wfe,   // wf rows 128..153, [26][64]
                                                   const float* __restrict__ wse,   // ws rows 128..153
                                                   const float* __restrict__ D,
                                                   const float* __restrict__ S,
                                                   float* __restrict__ acc, int ne) {
    __shared__ float sW[26][128];  // [k][0:64]=f, [k][64:128]=s
    int tid = threadIdx.x;
    for (int idx = tid; idx < 26 * 64; idx += 256) {
        int k = idx >> 6, j = idx & 63;
        sW[k][j] = wfe[idx];
        sW[k][64 + j] = wse[idx];
    }
    __syncthreads();

    int lane = tid & 31;
    int c2 = lane << 1;
    int gw = blockIdx.x * (blockDim.x >> 5) + (tid >> 5);
    int nw = gridDim.x * (blockDim.x >> 5);

    for (int e = gw; e < ne; e += nw) {
        int sv = __ldg(&src[e]);
        int dv = __ldg(&dst[e]);
        float d = __ldg(&elen[e]);

        const float2 af = *reinterpret_cast<const float2*>(&D[dv * 128 + c2]);
        const float2 asv = *reinterpret_cast<const float2*>(&D[dv * 128 + 64 + c2]);
        const float2 bfv = *reinterpret_cast<const float2*>(&S[sv * 128 + c2]);
        const float2 bsv = *reinterpret_cast<const float2*>(&S[sv * 128 + 64 + c2]);

        int k0 = (int)floorf(d * 5.0f + 0.5f);
        int klo = max(0, k0 - 4), khi = min(25, k0 + 4);
        float efx = 0.f, efy = 0.f, esx = 0.f, esy = 0.f;
        for (int k = klo; k <= khi; ++k) {
            float dm = d - (float)k * 0.2f;
            float g = __expf(dm * dm * -25.0f);  // exp(-(d-mu)^2 / 0.04)
            float2 wfv = *reinterpret_cast<const float2*>(&sW[k][c2]);
            float2 wsv = *reinterpret_cast<const float2*>(&sW[k][64 + c2]);
            efx = fmaf(g, wfv.x, efx);
            efy = fmaf(g, wfv.y, efy);
            esx = fmaf(g, wsv.x, esx);
            esy = fmaf(g, wsv.y, esy);
        }
        float zfx = af.x + bfv.x + efx;
        float zfy = af.y + bfv.y + efy;
        float zsx = asv.x + bsv.x + esx;
        float zsy = asv.y + bsv.y + esy;

        float sgx = __fdividef(1.0f, 1.0f + __expf(-zfx));
        float sgy = __fdividef(1.0f, 1.0f + __expf(-zfy));
        float spx = (zsx > 15.0f) ? zsx : __logf(1.0f + __expf(zsx));
        float spy = (zsy > 15.0f) ? zsy : __logf(1.0f + __expf(zsy));

        atomicAdd(&acc[dv * 64 + c2], sgx * spx);
        atomicAdd(&acc[dv * 64 + c2 + 1], sgy * spy);
    }
}

// ---------------- residual + activation ----------------
__global__ void finalize_kernel(float* __restrict__ h, const float* __restrict__ acc, int n, int act) {
    int i = blockIdx.x * blockDim.x + threadIdx.x;
    if (i >= n) return;
    float v = h[i] + acc[i];
    if (act) v = v > 0.0f ? v : 0.01f * v;
    h[i] = v;
}

// ---------------- readout layer 2: [N,64] @ [64,3] + b, warp per node ----------------
__global__ void desc2_kernel(const float* __restrict__ t3, const float* __restrict__ w2,
                             const float* __restrict__ b2, float* __restrict__ out, int n) {
    __shared__ float sw[192];
    __shared__ float sb[3];
    if (threadIdx.x < 192) sw[threadIdx.x] = w2[threadIdx.x];
    if (threadIdx.x < 3) sb[threadIdx.x] = b2[threadIdx.x];
    __syncthreads();
    int lane = threadIdx.x & 31;
    int gw = blockIdx.x * (blockDim.x >> 5) + (threadIdx.x >> 5);
    int nw = gridDim.x * (blockDim.x >> 5);
    for (int node = gw; node < n; node += nw) {
        float p0 = 0.f, p1 = 0.f, p2 = 0.f;
        for (int k = lane; k < 64; k += 32) {
            float v = t3[node * 64 + k];
            p0 = fmaf(v, sw[k * 3 + 0], p0);
            p1 = fmaf(v, sw[k * 3 + 1], p1);
            p2 = fmaf(v, sw[k * 3 + 2], p2);
        }
        for (int off = 16; off; off >>= 1) {
            p0 += __shfl_down_sync(0xffffffffu, p0, off);
            p1 += __shfl_down_sync(0xffffffffu, p1, off);
            p2 += __shfl_down_sync(0xffffffffu, p2, off);
        }
        if (lane == 0) {
            out[node * 3 + 0] = p0 + sb[0];
            out[node * 3 + 1] = p1 + sb[1];
            out[node * 3 + 2] = p2 + sb[2];
        }
    }
}

extern "C" void kernel_launch(void* const* d_in, const int* in_sizes, int n_in,
                              void* d_out, int out_size) {
    const float* x   = (const float*)d_in[0];
    const float* fs  = (const float*)d_in[1];
    const float* fn  = (const float*)d_in[2];
    const int* eidx  = (const int*)d_in[3];
    const float* elen = (const float*)d_in[4];
    const float* ew1 = (const float*)d_in[5];  const float* eb1 = (const float*)d_in[6];
    const float* ew2 = (const float*)d_in[7];  const float* eb2 = (const float*)d_in[8];
    const float* ew3 = (const float*)d_in[9];  const float* eb3 = (const float*)d_in[10];
    const float* dw1 = (const float*)d_in[23]; const float* db1 = (const float*)d_in[24];
    const float* dw2 = (const float*)d_in[25]; const float* db2 = (const float*)d_in[26];

    int nN = in_sizes[0] / 4;
    int nE = in_sizes[4];
    const int* src = eidx;        // edge_index[0]
    const int* dst = eidx + nE;   // edge_index[1]

    float *p_in8, *p_t1, *p_t2, *p_h, *p_D, *p_S, *p_acc, *p_t3;
    cudaGetSymbolAddress((void**)&p_in8, g_in8);
    cudaGetSymbolAddress((void**)&p_t1, g_t1);
    cudaGetSymbolAddress((void**)&p_t2, g_t2);
    cudaGetSymbolAddress((void**)&p_h, g_h);
    cudaGetSymbolAddress((void**)&p_D, g_D);
    cudaGetSymbolAddress((void**)&p_S, g_S);
    cudaGetSymbolAddress((void**)&p_acc, g_acc);
    cudaGetSymbolAddress((void**)&p_t3, g_t3);

    int gb = (nN + 31) / 32;

    // embedding MLP
    concat_kernel<<<(nN + 255) / 256, 256>>>(x, fs, fn, p_in8, nN);
    gemm_nodes_kernel<8, 128, 8, 32, 1><<<gb, 128>>>(p_in8, ew1, eb1, p_t1, nN, 128, 0);
    gemm_nodes_kernel<128, 128, 32, 32, 1><<<gb, 128>>>(p_t1, ew2, eb2, p_t2, nN, 128, 0);
    gemm_nodes_kernel<128, 64, 64, 32, 1><<<gb, 64>>>(p_t2, ew3, eb3, p_h, nN, 64, 0);

    // 3 CGConv layers
    for (int L = 0; L < 3; ++L) {
        const float* wf = (const float*)d_in[11 + 4 * L];
        const float* bf = (const float*)d_in[12 + 4 * L];
        const float* ws = (const float*)d_in[13 + 4 * L];
        const float* bs = (const float*)d_in[14 + 4 * L];
        // node projections: D = [h@wf[0:64]+bf | h@ws[0:64]+bs], S = [h@wf[64:128] | h@ws[64:128]]
        gemm_nodes_kernel<64, 64, 64, 32, 0><<<gb, 64>>>(p_h, wf, bf, p_D, nN, 128, 0);
        gemm_nodes_kernel<64, 64, 64, 32, 0><<<gb, 64>>>(p_h, ws, bs, p_D, nN, 128, 64);
        gemm_nodes_kernel<64, 64, 64, 32, 0><<<gb, 64>>>(p_h, wf + 64 * 64, nullptr, p_S, nN, 128, 0);
        gemm_nodes_kernel<64, 64, 64, 32, 0><<<gb, 64>>>(p_h, ws + 64 * 64, nullptr, p_S, nN, 128, 64);
        zero_kernel<<<(nN * 16 + 255) / 256, 256>>>(p_acc, nN * 16);
        edge_kernel<<<2048, 256>>>(src, dst, elen, wf + 128 * 64, ws + 128 * 64, p_D, p_S, p_acc, nE);
        finalize_kernel<<<(nN * 64 + 255) / 256, 256>>>(p_h, p_acc, nN * 64, L < 2 ? 1 : 0);
    }

    // readout
    gemm_nodes_kernel<64, 64, 64, 32, 2><<<gb, 64>>>(p_h, dw1, db1, p_t3, nN, 64, 0);
    desc2_kernel<<<1024, 256>>>(p_t3, dw2, db2, (float*)d_out, nN);
}

// round 3
// speedup vs baseline: 1.4440x; 1.4440x over previous
#include <cuda_runtime.h>
#include <math.h>

#define NNODES 50000
#define NEDGES 1200000

// ---------------- scratch (device globals: no allocation allowed) ----------------
__device__ float g_in8[NNODES * 8];
__device__ float g_t1[NNODES * 128];
__device__ float g_t2[NNODES * 128];
__device__ float g_h[NNODES * 64];      // current node features
__device__ float g_D[NNODES * 128];     // [Af | As] dst-side projections (bias folded)
__device__ float g_S[NNODES * 128];     // [Bf | Bs] src-side projections
__device__ float g_t3[NNODES * 64];     // readout hidden
__device__ int   g_cnt[NNODES * 2];     // [deg | cursor]
__device__ int   g_rowstart[NNODES + 1];
__device__ int   g_csr_src[NEDGES];
__device__ float4 g_gA[NEDGES];         // g0..g3
__device__ float4 g_gB[NEDGES];         // g4..g6, bitcast(klo)

// ---------------- concat [x|forces_stack|forces_norm] -> [N,8] ----------------
__global__ void concat_kernel(const float* __restrict__ x, const float* __restrict__ fs,
                              const float* __restrict__ fn, float* __restrict__ out, int n) {
    int i = blockIdx.x * blockDim.x + threadIdx.x;
    if (i >= n) return;
    float4 xv = *reinterpret_cast<const float4*>(&x[i * 4]);
    out[i * 8 + 0] = xv.x;
    out[i * 8 + 1] = xv.y;
    out[i * 8 + 2] = xv.z;
    out[i * 8 + 3] = xv.w;
    out[i * 8 + 4] = fs[i * 3 + 0];
    out[i * 8 + 5] = fs[i * 3 + 1];
    out[i * 8 + 6] = fs[i * 3 + 2];
    out[i * 8 + 7] = fn[i];
}

// ---------------- CSR build ----------------
__global__ void zero_int_kernel(int* __restrict__ p, int n) {
    int i = blockIdx.x * blockDim.x + threadIdx.x;
    if (i < n) p[i] = 0;
}

__global__ void hist_kernel(const int* __restrict__ dst, int* __restrict__ deg, int ne) {
    int e = blockIdx.x * blockDim.x + threadIdx.x;
    if (e < ne) atomicAdd(&deg[dst[e]], 1);
}

// single-block exclusive scan over nN ints -> rowstart[0..nN]
__global__ void scan_kernel(const int* __restrict__ deg, int* __restrict__ rowstart, int nN) {
    __shared__ int warpsums[32];
    __shared__ int soff;
    int tid = threadIdx.x;
    int lane = tid & 31, wid = tid >> 5;
    if (tid == 0) soff = 0;
    __syncthreads();
    for (int base = 0; base < nN; base += 1024) {
        int i = base + tid;
        int v = (i < nN) ? deg[i] : 0;
        int x = v;
#pragma unroll
        for (int o = 1; o < 32; o <<= 1) {
            int t = __shfl_up_sync(0xffffffffu, x, o);
            if (lane >= o) x += t;
        }
        if (lane == 31) warpsums[wid] = x;
        __syncthreads();
        if (wid == 0) {
            int y = warpsums[lane];
#pragma unroll
            for (int o = 1; o < 32; o <<= 1) {
                int t = __shfl_up_sync(0xffffffffu, y, o);
                if (lane >= o) y += t;
            }
            warpsums[lane] = y;
        }
        __syncthreads();
        int incl = x + (wid ? warpsums[wid - 1] : 0);
        int off = soff;
        if (i < nN) rowstart[i] = off + incl - v;
        __syncthreads();
        if (tid == 1023) soff = off + warpsums[31];
        __syncthreads();
    }
    if (tid == 0) rowstart[nN] = soff;
}

// scatter edges into CSR order (by dst) + precompute 7-term gaussian window
__global__ void scatter_kernel(const int* __restrict__ src, const int* __restrict__ dst,
                               const float* __restrict__ elen,
                               const int* __restrict__ rowstart, int* __restrict__ cursor,
                               int* __restrict__ csr_src,
                               float4* __restrict__ gA, float4* __restrict__ gB, int ne) {
    int e = blockIdx.x * blockDim.x + threadIdx.x;
    if (e >= ne) return;
    int dv = dst[e];
    int slot = rowstart[dv] + atomicAdd(&cursor[dv], 1);
    csr_src[slot] = src[e];
    float d = elen[e];
    int k0 = (int)rintf(d * 5.0f);
    int klo = min(max(k0 - 3, 0), 19);
    float g[7];
#pragma unroll
    for (int j = 0; j < 7; ++j) {
        float dm = d - (float)(klo + j) * 0.2f;
        g[j] = __expf(-25.0f * dm * dm);
    }
    gA[slot] = make_float4(g[0], g[1], g[2], g[3]);
    gB[slot] = make_float4(g[4], g[5], g[6], __int_as_float(klo));
}

// ---------------- node GEMM v2: out[n][ocol+j] = act(bias[j] + sum_k in[n][k]*W[k][j]) ----
// block = J*YB threads; NB nodes per block; each thread NB/YB accumulators.
template <int K, int J, int YB, int NB, int KT, int ACT>
__global__ void __launch_bounds__(J * YB) gemm2_kernel(const float* __restrict__ in,
                                                       const float* __restrict__ W,
                                                       const float* __restrict__ bias,
                                                       float* __restrict__ out, int nN,
                                                       int ostride, int ocol) {
    constexpr int NBY = NB / YB;
    __shared__ float sIn[NB][K];
    __shared__ float sW[KT][J];
    int tid = threadIdx.x;
    int col = tid % J;
    int ys = tid / J;
    int nb = blockIdx.x * NB;

    for (int idx = tid * 4; idx < NB * K; idx += J * YB * 4) {
        int n = idx / K, k = idx % K;
        int gn = nb + n;
        float4 v = (gn < nN) ? *reinterpret_cast<const float4*>(&in[gn * K + k])
                             : make_float4(0.f, 0.f, 0.f, 0.f);
        *reinterpret_cast<float4*>(&sIn[n][k]) = v;
    }
    float bv = bias ? __ldg(&bias[col]) : 0.0f;
    float acc[NBY];
#pragma unroll
    for (int n = 0; n < NBY; n++) acc[n] = bv;

    for (int k0 = 0; k0 < K; k0 += KT) {
        __syncthreads();
        for (int r = ys; r < KT; r += YB) sW[r][col] = W[(k0 + r) * J + col];
        __syncthreads();
#pragma unroll
        for (int k = 0; k < KT; k += 4) {
            float w0 = sW[k][col], w1 = sW[k + 1][col], w2 = sW[k + 2][col], w3 = sW[k + 3][col];
#pragma unroll
            for (int n = 0; n < NBY; ++n) {
                float4 v = *reinterpret_cast<const float4*>(&sIn[ys * NBY + n][k0 + k]);
                float a = acc[n];
                a = fmaf(v.x, w0, a);
                a = fmaf(v.y, w1, a);
                a = fmaf(v.z, w2, a);
                a = fmaf(v.w, w3, a);
                acc[n] = a;
            }
        }
    }
#pragma unroll
    for (int n = 0; n < NBY; n++) {
        int gn = nb + ys * NBY + n;
        if (gn < nN) {
            float v = acc[n];
            if (ACT == 1) v = v > 0.0f ? v : 0.01f * v;   // leaky
            else if (ACT == 2) v = fmaxf(v, 0.0f);        // relu
            out[gn * ostride + ocol + col] = v;
        }
    }
}

// ---------------- fused conv projections: D=[h@wf0+bf | h@ws0+bs], S=[h@wf1 | h@ws1] ----
template <int NB>
__global__ void __launch_bounds__(256) convproj_kernel(const float* __restrict__ h,
                                                       const float* __restrict__ wf,
                                                       const float* __restrict__ bf,
                                                       const float* __restrict__ ws,
                                                       const float* __restrict__ bs,
                                                       float* __restrict__ D,
                                                       float* __restrict__ S, int nN) {
    __shared__ float sIn[NB][64];
    __shared__ float sW[16][256];
    int tid = threadIdx.x;
    int seg = tid >> 6;       // 0:D.f 1:D.s 2:S.f 3:S.s
    int jj = tid & 63;
    int nb = blockIdx.x * NB;

    for (int idx = tid * 4; idx < NB * 64; idx += 1024) {
        int n = idx >> 6, k = idx & 63;
        int gn = nb + n;
        float4 v = (gn < nN) ? *reinterpret_cast<const float4*>(&h[gn * 64 + k])
                             : make_float4(0.f, 0.f, 0.f, 0.f);
        *reinterpret_cast<float4*>(&sIn[n][k]) = v;
    }
    const float* Wb = (seg & 1) ? ws : wf;
    int rowoff = (seg & 2) ? 64 : 0;
    float bv = 0.0f;
    if (seg == 0) bv = __ldg(&bf[jj]);
    if (seg == 1) bv = __ldg(&bs[jj]);
    float acc[NB];
#pragma unroll
    for (int n = 0; n < NB; n++) acc[n] = bv;

    for (int k0 = 0; k0 < 64; k0 += 16) {
        __syncthreads();
#pragma unroll
        for (int r = 0; r < 16; ++r) sW[r][tid] = Wb[(rowoff + k0 + r) * 64 + jj];
        __syncthreads();
#pragma unroll
        for (int k = 0; k < 16; k += 4) {
            float w0 = sW[k][tid], w1 = sW[k + 1][tid], w2 = sW[k + 2][tid], w3 = sW[k + 3][tid];
#pragma unroll
            for (int n = 0; n < NB; ++n) {
                float4 v = *reinterpret_cast<const float4*>(&sIn[n][k0 + k]);
                float a = acc[n];
                a = fmaf(v.x, w0, a);
                a = fmaf(v.y, w1, a);
                a = fmaf(v.z, w2, a);
                a = fmaf(v.w, w3, a);
                acc[n] = a;
            }
        }
    }
    float* outp = (seg & 2) ? S : D;
    int colo = ((seg & 1) << 6) + jj;
#pragma unroll
    for (int n = 0; n < NB; n++) {
        int gn = nb + n;
        if (gn < nN) outp[gn * 128 + colo] = acc[n];
    }
}

// ---------------- edge kernel: warp per dst node, register accumulation, no atomics ----
__global__ void __launch_bounds__(256) edge2_kernel(const float* __restrict__ D,
                                                    const float* __restrict__ S,
                                                    float* __restrict__ h,
                                                    const int* __restrict__ rowstart,
                                                    const int* __restrict__ csr_src,
                                                    const float4* __restrict__ gA,
                                                    const float4* __restrict__ gB,
                                                    const float* __restrict__ wfe,
                                                    const float* __restrict__ wse,
                                                    int nN, int act) {
    __shared__ float4 sW4[26][32];  // [k][lane] = (wf[k][2l], wf[k][2l+1], ws[k][2l], ws[k][2l+1])
    int tid = threadIdx.x;
    for (int idx = tid; idx < 26 * 32; idx += 256) {
        int k = idx >> 5, l = idx & 31;
        sW4[k][l] = make_float4(wfe[k * 64 + 2 * l], wfe[k * 64 + 2 * l + 1],
                                wse[k * 64 + 2 * l], wse[k * 64 + 2 * l + 1]);
    }
    __syncthreads();

    int lane = tid & 31;
    int node = blockIdx.x * 8 + (tid >> 5);
    if (node >= nN) return;
    int c2 = lane << 1;

    const float2 af = *reinterpret_cast<const float2*>(&D[node * 128 + c2]);
    const float2 as = *reinterpret_cast<const float2*>(&D[node * 128 + 64 + c2]);
    const float2 hm = *reinterpret_cast<const float2*>(&h[node * 64 + c2]);
    float mx = 0.0f, my = 0.0f;

    int rs = __ldg(&rowstart[node]);
    int re = __ldg(&rowstart[node + 1]);
#pragma unroll 2
    for (int s = rs; s < re; ++s) {
        int sv = __ldg(&csr_src[s]);
        float4 ga = __ldg(&gA[s]);
        float4 gb = __ldg(&gB[s]);
        int klo = __float_as_int(gb.w);
        const float2 bf = *reinterpret_cast<const float2*>(&S[sv * 128 + c2]);
        const float2 bs = *reinterpret_cast<const float2*>(&S[sv * 128 + 64 + c2]);

        const float4* wp = &sW4[klo][lane];
        float efx = 0.f, efy = 0.f, esx = 0.f, esy = 0.f;
        float4 w;
#define GSTEP(G, OFF)                                        \
        w = wp[(OFF) * 32];                                  \
        efx = fmaf((G), w.x, efx); efy = fmaf((G), w.y, efy);\
        esx = fmaf((G), w.z, esx); esy = fmaf((G), w.w, esy);
        GSTEP(ga.x, 0) GSTEP(ga.y, 1) GSTEP(ga.z, 2) GSTEP(ga.w, 3)
        GSTEP(gb.x, 4) GSTEP(gb.y, 5) GSTEP(gb.z, 6)
#undef GSTEP

        float zfx = af.x + bf.x + efx;
        float zfy = af.y + bf.y + efy;
        float zsx = as.x + bs.x + esx;
        float zsy = as.y + bs.y + esy;

        float sgx = __fdividef(1.0f, 1.0f + __expf(-zfx));
        float sgy = __fdividef(1.0f, 1.0f + __expf(-zfy));
        float spx = (zsx > 15.0f) ? zsx : __logf(1.0f + __expf(zsx));
        float spy = (zsy > 15.0f) ? zsy : __logf(1.0f + __expf(zsy));

        mx = fmaf(sgx, spx, mx);
        my = fmaf(sgy, spy, my);
    }
    float ox = hm.x + mx, oy = hm.y + my;
    if (act) {
        ox = ox > 0.0f ? ox : 0.01f * ox;
        oy = oy > 0.0f ? oy : 0.01f * oy;
    }
    *reinterpret_cast<float2*>(&h[node * 64 + c2]) = make_float2(ox, oy);
}

// ---------------- readout layer 2: [N,64] @ [64,3] + b, warp per node ----------------
__global__ void desc2_kernel(const float* __restrict__ t3, const float* __restrict__ w2,
                             const float* __restrict__ b2, float* __restrict__ out, int n) {
    __shared__ float sw[192];
    __shared__ float sb[3];
    if (threadIdx.x < 192) sw[threadIdx.x] = w2[threadIdx.x];
    if (threadIdx.x < 3) sb[threadIdx.x] = b2[threadIdx.x];
    __syncthreads();
    int lane = threadIdx.x & 31;
    int gw = blockIdx.x * (blockDim.x >> 5) + (threadIdx.x >> 5);
    int nw = gridDim.x * (blockDim.x >> 5);
    for (int node = gw; node < n; node += nw) {
        float p0 = 0.f, p1 = 0.f, p2 = 0.f;
        for (int k = lane; k < 64; k += 32) {
            float v = t3[node * 64 + k];
            p0 = fmaf(v, sw[k * 3 + 0], p0);
            p1 = fmaf(v, sw[k * 3 + 1], p1);
            p2 = fmaf(v, sw[k * 3 + 2], p2);
        }
        for (int off = 16; off; off >>= 1) {
            p0 += __shfl_down_sync(0xffffffffu, p0, off);
            p1 += __shfl_down_sync(0xffffffffu, p1, off);
            p2 += __shfl_down_sync(0xffffffffu, p2, off);
        }
        if (lane == 0) {
            out[node * 3 + 0] = p0 + sb[0];
            out[node * 3 + 1] = p1 + sb[1];
            out[node * 3 + 2] = p2 + sb[2];
        }
    }
}

extern "C" void kernel_launch(void* const* d_in, const int* in_sizes, int n_in,
                              void* d_out, int out_size) {
    const float* x    = (const float*)d_in[0];
    const float* fs   = (const float*)d_in[1];
    const float* fn   = (const float*)d_in[2];
    const int*   eidx = (const int*)d_in[3];
    const float* elen = (const float*)d_in[4];
    const float* ew1 = (const float*)d_in[5];  const float* eb1 = (const float*)d_in[6];
    const float* ew2 = (const float*)d_in[7];  const float* eb2 = (const float*)d_in[8];
    const float* ew3 = (const float*)d_in[9];  const float* eb3 = (const float*)d_in[10];
    const float* dw1 = (const float*)d_in[23]; const float* db1 = (const float*)d_in[24];
    const float* dw2 = (const float*)d_in[25]; const float* db2 = (const float*)d_in[26];

    int nN = in_sizes[0] / 4;
    int nE = in_sizes[4];
    const int* src = eidx;        // edge_index[0]
    const int* dst = eidx + nE;   // edge_index[1]

    float *p_in8, *p_t1, *p_t2, *p_h, *p_D, *p_S, *p_t3;
    int *p_cnt, *p_rowstart, *p_csr_src;
    float4 *p_gA, *p_gB;
    cudaGetSymbolAddress((void**)&p_in8, g_in8);
    cudaGetSymbolAddress((void**)&p_t1, g_t1);
    cudaGetSymbolAddress((void**)&p_t2, g_t2);
    cudaGetSymbolAddress((void**)&p_h, g_h);
    cudaGetSymbolAddress((void**)&p_D, g_D);
    cudaGetSymbolAddress((void**)&p_S, g_S);
    cudaGetSymbolAddress((void**)&p_t3, g_t3);
    cudaGetSymbolAddress((void**)&p_cnt, g_cnt);
    cudaGetSymbolAddress((void**)&p_rowstart, g_rowstart);
    cudaGetSymbolAddress((void**)&p_csr_src, g_csr_src);
    cudaGetSymbolAddress((void**)&p_gA, g_gA);
    cudaGetSymbolAddress((void**)&p_gB, g_gB);

    int* p_deg = p_cnt;
    int* p_cur = p_cnt + NNODES;

    // ---- CSR build (per launch; graph-capturable, deterministic up to fp sum order) ----
    zero_int_kernel<<<(2 * nN + 255) / 256, 256>>>(p_cnt, 2 * nN);
    hist_kernel<<<(nE + 255) / 256, 256>>>(dst, p_deg, nE);
    scan_kernel<<<1, 1024>>>(p_deg, p_rowstart, nN);
    scatter_kernel<<<(nE + 255) / 256, 256>>>(src, dst, elen, p_rowstart, p_cur,
                                              p_csr_src, p_gA, p_gB, nE);

    // ---- embedding MLP ----
    concat_kernel<<<(nN + 255) / 256, 256>>>(x, fs, fn, p_in8, nN);
    gemm2_kernel<8, 128, 2, 16, 8, 1><<<(nN + 15) / 16, 256>>>(p_in8, ew1, eb1, p_t1, nN, 128, 0);
    gemm2_kernel<128, 128, 2, 16, 32, 1><<<(nN + 15) / 16, 256>>>(p_t1, ew2, eb2, p_t2, nN, 128, 0);
    gemm2_kernel<128, 64, 4, 32, 32, 1><<<(nN + 31) / 32, 256>>>(p_t2, ew3, eb3, p_h, nN, 64, 0);

    // ---- 3 CGConv layers ----
    for (int L = 0; L < 3; ++L) {
        const float* wf = (const float*)d_in[11 + 4 * L];
        const float* bf = (const float*)d_in[12 + 4 * L];
        const float* ws = (const float*)d_in[13 + 4 * L];
        const float* bs = (const float*)d_in[14 + 4 * L];
        convproj_kernel<16><<<(nN + 15) / 16, 256>>>(p_h, wf, bf, ws, bs, p_D, p_S, nN);
        edge2_kernel<<<(nN + 7) / 8, 256>>>(p_D, p_S, p_h, p_rowstart, p_csr_src,
                                            p_gA, p_gB, wf + 128 * 64, ws + 128 * 64,
                                            nN, L < 2 ? 1 : 0);
    }

    // ---- readout ----
    gemm2_kernel<64, 64, 4, 32, 64, 2><<<(nN + 31) / 32, 256>>>(p_h, dw1, db1, p_t3, nN, 64, 0);
    desc2_kernel<<<1024, 256>>>(p_t3, dw2, db2, (float*)d_out, nN);
}

// round 4
// speedup vs baseline: 1.6400x; 1.1358x over previous
#include <cuda_runtime.h>
#include <math.h>

#define NNODES 50000
#define NEDGES 1200000

// ---------------- scratch (device globals: no allocation allowed) ----------------
__device__ float g_in8[NNODES * 8];
__device__ float g_t1[NNODES * 128];
__device__ float g_t2[NNODES * 128];
__device__ float g_h[NNODES * 64];      // current node features
__device__ float g_D[NNODES * 128];     // packed dst proj: float4[l]=(Df2l,Df2l+1,Ds2l,Ds2l+1)
__device__ float g_S[NNODES * 128];     // packed src proj, same layout
__device__ float g_t3[NNODES * 64];     // readout hidden
__device__ int   g_cnt[NNODES * 2];     // [deg | cursor]
__device__ int   g_rowstart[NNODES + 1];
__device__ int   g_csr_src[NEDGES];
__device__ float4 g_gA[NEDGES];         // g0..g3
__device__ float2 g_gB[NEDGES];         // g4, bitcast(klo)

// ---------------- concat [x|forces_stack|forces_norm] -> [N,8] ----------------
__global__ void concat_kernel(const float* __restrict__ x, const float* __restrict__ fs,
                              const float* __restrict__ fn, float* __restrict__ out, int n) {
    int i = blockIdx.x * blockDim.x + threadIdx.x;
    if (i >= n) return;
    float4 xv = *reinterpret_cast<const float4*>(&x[i * 4]);
    out[i * 8 + 0] = xv.x;
    out[i * 8 + 1] = xv.y;
    out[i * 8 + 2] = xv.z;
    out[i * 8 + 3] = xv.w;
    out[i * 8 + 4] = fs[i * 3 + 0];
    out[i * 8 + 5] = fs[i * 3 + 1];
    out[i * 8 + 6] = fs[i * 3 + 2];
    out[i * 8 + 7] = fn[i];
}

// ---------------- CSR build ----------------
__global__ void zero_int_kernel(int* __restrict__ p, int n) {
    int i = blockIdx.x * blockDim.x + threadIdx.x;
    if (i < n) p[i] = 0;
}

__global__ void hist_kernel(const int* __restrict__ dst, int* __restrict__ deg, int ne) {
    int e = blockIdx.x * blockDim.x + threadIdx.x;
    if (e < ne) atomicAdd(&deg[dst[e]], 1);
}

// single-block exclusive scan over nN ints -> rowstart[0..nN]
__global__ void scan_kernel(const int* __restrict__ deg, int* __restrict__ rowstart, int nN) {
    __shared__ int warpsums[32];
    __shared__ int soff;
    int tid = threadIdx.x;
    int lane = tid & 31, wid = tid >> 5;
    if (tid == 0) soff = 0;
    __syncthreads();
    for (int base = 0; base < nN; base += 1024) {
        int i = base + tid;
        int v = (i < nN) ? deg[i] : 0;
        int x = v;
#pragma unroll
        for (int o = 1; o < 32; o <<= 1) {
            int t = __shfl_up_sync(0xffffffffu, x, o);
            if (lane >= o) x += t;
        }
        if (lane == 31) warpsums[wid] = x;
        __syncthreads();
        if (wid == 0) {
            int y = warpsums[lane];
#pragma unroll
            for (int o = 1; o < 32; o <<= 1) {
                int t = __shfl_up_sync(0xffffffffu, y, o);
                if (lane >= o) y += t;
            }
            warpsums[lane] = y;
        }
        __syncthreads();
        int incl = x + (wid ? warpsums[wid - 1] : 0);
        int off = soff;
        if (i < nN) rowstart[i] = off + incl - v;
        __syncthreads();
        if (tid == 1023) soff = off + warpsums[31];
        __syncthreads();
    }
    if (tid == 0) rowstart[nN] = soff;
}

// scatter edges into CSR order (by dst) + precompute 5-term gaussian window
// dropped terms <= exp(-6.25)*|w| ~ 1.5e-4 in z; well under the 1e-3 rel_err budget
__global__ void scatter_kernel(const int* __restrict__ src, const int* __restrict__ dst,
                               const float* __restrict__ elen,
                               const int* __restrict__ rowstart, int* __restrict__ cursor,
                               int* __restrict__ csr_src,
                               float4* __restrict__ gA, float2* __restrict__ gB, int ne) {
    int e = blockIdx.x * blockDim.x + threadIdx.x;
    if (e >= ne) return;
    int dv = dst[e];
    int slot = rowstart[dv] + atomicAdd(&cursor[dv], 1);
    csr_src[slot] = src[e];
    float d = elen[e];
    int k0 = (int)rintf(d * 5.0f);
    int klo = min(max(k0 - 2, 0), 21);
    float g[5];
#pragma unroll
    for (int j = 0; j < 5; ++j) {
        float dm = d - (float)(klo + j) * 0.2f;
        g[j] = __expf(-25.0f * dm * dm);
    }
    gA[slot] = make_float4(g[0], g[1], g[2], g[3]);
    gB[slot] = make_float2(g[4], __int_as_float(klo));
}

// ---------------- node GEMM v2: out[n][ocol+j] = act(bias[j] + sum_k in[n][k]*W[k][j]) ----
template <int K, int J, int YB, int NB, int KT, int ACT>
__global__ void __launch_bounds__(J * YB) gemm2_kernel(const float* __restrict__ in,
                                                       const float* __restrict__ W,
                                                       const float* __restrict__ bias,
                                                       float* __restrict__ out, int nN,
                                                       int ostride, int ocol) {
    constexpr int NBY = NB / YB;
    __shared__ float sIn[NB][K];
    __shared__ float sW[KT][J];
    int tid = threadIdx.x;
    int col = tid % J;
    int ys = tid / J;
    int nb = blockIdx.x * NB;

    for (int idx = tid * 4; idx < NB * K; idx += J * YB * 4) {
        int n = idx / K, k = idx % K;
        int gn = nb + n;
        float4 v = (gn < nN) ? *reinterpret_cast<const float4*>(&in[gn * K + k])
                             : make_float4(0.f, 0.f, 0.f, 0.f);
        *reinterpret_cast<float4*>(&sIn[n][k]) = v;
    }
    float bv = bias ? __ldg(&bias[col]) : 0.0f;
    float acc[NBY];
#pragma unroll
    for (int n = 0; n < NBY; n++) acc[n] = bv;

    for (int k0 = 0; k0 < K; k0 += KT) {
        __syncthreads();
        for (int r = ys; r < KT; r += YB) sW[r][col] = W[(k0 + r) * J + col];
        __syncthreads();
#pragma unroll
        for (int k = 0; k < KT; k += 4) {
            float w0 = sW[k][col], w1 = sW[k + 1][col], w2 = sW[k + 2][col], w3 = sW[k + 3][col];
#pragma unroll
            for (int n = 0; n < NBY; ++n) {
                float4 v = *reinterpret_cast<const float4*>(&sIn[ys * NBY + n][k0 + k]);
                float a = acc[n];
                a = fmaf(v.x, w0, a);
                a = fmaf(v.y, w1, a);
                a = fmaf(v.z, w2, a);
                a = fmaf(v.w, w3, a);
                acc[n] = a;
            }
        }
    }
#pragma unroll
    for (int n = 0; n < NBY; n++) {
        int gn = nb + ys * NBY + n;
        if (gn < nN) {
            float v = acc[n];
            if (ACT == 1) v = v > 0.0f ? v : 0.01f * v;   // leaky
            else if (ACT == 2) v = fmaxf(v, 0.0f);        // relu
            out[gn * ostride + ocol + col] = v;
        }
    }
}

// ---------------- fused conv projections, packed output ----------------
// Thread tid owns packed element r=tid&127 of D (tid<128) or S (tid>=128):
//   l=r>>2, c=r&3; j=2l+(c&1); matrix = (c<2 ? wf : ws); rowoff = (S ? 64 : 0)
// Output float4[l] = (f_{2l}, f_{2l+1}, s_{2l}, s_{2l+1}); stores fully coalesced.
template <int NB>
__global__ void __launch_bounds__(256) convproj_kernel(const float* __restrict__ h,
                                                       const float* __restrict__ wf,
                                                       const float* __restrict__ bf,
                                                       const float* __restrict__ ws,
                                                       const float* __restrict__ bs,
                                                       float* __restrict__ D,
                                                       float* __restrict__ S, int nN) {
    __shared__ float sIn[NB][64];
    __shared__ float sW[16][256];
    int tid = threadIdx.x;
    int part = tid >> 7;          // 0: D (dst rows of W), 1: S (src rows)
    int r = tid & 127;
    int c = r & 3;
    int j = ((r >> 2) << 1) + (c & 1);
    bool usef = (c < 2);
    int rowoff = part ? 64 : 0;
    const float* Wb = usef ? wf : ws;
    int nb = blockIdx.x * NB;

    for (int idx = tid * 4; idx < NB * 64; idx += 1024) {
        int n = idx >> 6, k = idx & 63;
        int gn = nb + n;
        float4 v = (gn < nN) ? *reinterpret_cast<const float4*>(&h[gn * 64 + k])
                             : make_float4(0.f, 0.f, 0.f, 0.f);
        *reinterpret_cast<float4*>(&sIn[n][k]) = v;
    }
    float bv = 0.0f;
    if (part == 0) bv = usef ? __ldg(&bf[j]) : __ldg(&bs[j]);
    float acc[NB];
#pragma unroll
    for (int n = 0; n < NB; n++) acc[n] = bv;

    for (int k0 = 0; k0 < 64; k0 += 16) {
        __syncthreads();
#pragma unroll
        for (int rr = 0; rr < 16; ++rr) sW[rr][tid] = Wb[(rowoff + k0 + rr) * 64 + j];
        __syncthreads();
#pragma unroll
        for (int k = 0; k < 16; k += 4) {
            float w0 = sW[k][tid], w1 = sW[k + 1][tid], w2 = sW[k + 2][tid], w3 = sW[k + 3][tid];
#pragma unroll
            for (int n = 0; n < NB; ++n) {
                float4 v = *reinterpret_cast<const float4*>(&sIn[n][k0 + k]);
                float a = acc[n];
                a = fmaf(v.x, w0, a);
                a = fmaf(v.y, w1, a);
                a = fmaf(v.z, w2, a);
                a = fmaf(v.w, w3, a);
                acc[n] = a;
            }
        }
    }
    float* outp = part ? S : D;
#pragma unroll
    for (int n = 0; n < NB; n++) {
        int gn = nb + n;
        if (gn < nN) outp[gn * 128 + r] = acc[n];
    }
}

// ---------------- edge kernel: warp per dst node, packed gathers, no atomics ----------------
__global__ void __launch_bounds__(256) edge2_kernel(const float4* __restrict__ D4,
                                                    const float4* __restrict__ S4,
                                                    float* __restrict__ h,
                                                    const int* __restrict__ rowstart,
                                                    const int* __restrict__ csr_src,
                                                    const float4* __restrict__ gA,
                                                    const float2* __restrict__ gB,
                                                    const float* __restrict__ wfe,
                                                    const float* __restrict__ wse,
                                                    int nN, int act) {
    __shared__ float4 sW4[26][32];  // [k][lane] = (wf[k][2l], wf[k][2l+1], ws[k][2l], ws[k][2l+1])
    int tid = threadIdx.x;
    for (int idx = tid; idx < 26 * 32; idx += 256) {
        int k = idx >> 5, l = idx & 31;
        sW4[k][l] = make_float4(wfe[k * 64 + 2 * l], wfe[k * 64 + 2 * l + 1],
                                wse[k * 64 + 2 * l], wse[k * 64 + 2 * l + 1]);
    }
    __syncthreads();

    int lane = tid & 31;
    int node = blockIdx.x * 8 + (tid >> 5);
    if (node >= nN) return;
    int c2 = lane << 1;

    const float4 a4 = __ldg(&D4[node * 32 + lane]);  // (af.x, af.y, as.x, as.y)
    const float2 hm = *reinterpret_cast<const float2*>(&h[node * 64 + c2]);
    float mx = 0.0f, my = 0.0f;

    int rs = __ldg(&rowstart[node]);
    int re = __ldg(&rowstart[node + 1]);
#pragma unroll 2
    for (int s = rs; s < re; ++s) {
        int sv = __ldg(&csr_src[s]);
        float4 ga = __ldg(&gA[s]);
        float2 gb = __ldg(&gB[s]);
        int klo = __float_as_int(gb.y);
        const float4 b4 = __ldg(&S4[sv * 32 + lane]);  // (bf.x, bf.y, bs.x, bs.y)

        const float4* wp = &sW4[klo][lane];
        float efx = 0.f, efy = 0.f, esx = 0.f, esy = 0.f;
        float4 w;
#define GSTEP(G, OFF)                                        \
        w = wp[(OFF) * 32];                                  \
        efx = fmaf((G), w.x, efx); efy = fmaf((G), w.y, efy);\
        esx = fmaf((G), w.z, esx); esy = fmaf((G), w.w, esy);
        GSTEP(ga.x, 0) GSTEP(ga.y, 1) GSTEP(ga.z, 2) GSTEP(ga.w, 3) GSTEP(gb.x, 4)
#undef GSTEP

        float zfx = a4.x + b4.x + efx;
        float zfy = a4.y + b4.y + efy;
        float zsx = a4.z + b4.z + esx;
        float zsy = a4.w + b4.w + esy;

        float sgx = __fdividef(1.0f, 1.0f + __expf(-zfx));
        float sgy = __fdividef(1.0f, 1.0f + __expf(-zfy));
        float spx = (zsx > 15.0f) ? zsx : __logf(1.0f + __expf(zsx));
        float spy = (zsy > 15.0f) ? zsy : __logf(1.0f + __expf(zsy));

        mx = fmaf(sgx, spx, mx);
        my = fmaf(sgy, spy, my);
    }
    float ox = hm.x + mx, oy = hm.y + my;
    if (act) {
        ox = ox > 0.0f ? ox : 0.01f * ox;
        oy = oy > 0.0f ? oy : 0.01f * oy;
    }
    *reinterpret_cast<float2*>(&h[node * 64 + c2]) = make_float2(ox, oy);
}

// ---------------- readout layer 2: [N,64] @ [64,3] + b, warp per node ----------------
__global__ void desc2_kernel(const float* __restrict__ t3, const float* __restrict__ w2,
                             const float* __restrict__ b2, float* __restrict__ out, int n) {
    __shared__ float sw[192];
    __shared__ float sb[3];
    if (threadIdx.x < 192) sw[threadIdx.x] = w2[threadIdx.x];
    if (threadIdx.x < 3) sb[threadIdx.x] = b2[threadIdx.x];
    __syncthreads();
    int lane = threadIdx.x & 31;
    int gw = blockIdx.x * (blockDim.x >> 5) + (threadIdx.x >> 5);
    int nw = gridDim.x * (blockDim.x >> 5);
    for (int node = gw; node < n; node += nw) {
        float p0 = 0.f, p1 = 0.f, p2 = 0.f;
        for (int k = lane; k < 64; k += 32) {
            float v = t3[node * 64 + k];
            p0 = fmaf(v, sw[k * 3 + 0], p0);
            p1 = fmaf(v, sw[k * 3 + 1], p1);
            p2 = fmaf(v, sw[k * 3 + 2], p2);
        }
        for (int off = 16; off; off >>= 1) {
            p0 += __shfl_down_sync(0xffffffffu, p0, off);
            p1 += __shfl_down_sync(0xffffffffu, p1, off);
            p2 += __shfl_down_sync(0xffffffffu, p2, off);
        }
        if (lane == 0) {
            out[node * 3 + 0] = p0 + sb[0];
            out[node * 3 + 1] = p1 + sb[1];
            out[node * 3 + 2] = p2 + sb[2];
        }
    }
}

extern "C" void kernel_launch(void* const* d_in, const int* in_sizes, int n_in,
                              void* d_out, int out_size) {
    const float* x    = (const float*)d_in[0];
    const float* fs   = (const float*)d_in[1];
    const float* fn   = (const float*)d_in[2];
    const int*   eidx = (const int*)d_in[3];
    const float* elen = (const float*)d_in[4];
    const float* ew1 = (const float*)d_in[5];  const float* eb1 = (const float*)d_in[6];
    const float* ew2 = (const float*)d_in[7];  const float* eb2 = (const float*)d_in[8];
    const float* ew3 = (const float*)d_in[9];  const float* eb3 = (const float*)d_in[10];
    const float* dw1 = (const float*)d_in[23]; const float* db1 = (const float*)d_in[24];
    const float* dw2 = (const float*)d_in[25]; const float* db2 = (const float*)d_in[26];

    int nN = in_sizes[0] / 4;
    int nE = in_sizes[4];
    const int* src = eidx;        // edge_index[0]
    const int* dst = eidx + nE;   // edge_index[1]

    float *p_in8, *p_t1, *p_t2, *p_h, *p_D, *p_S, *p_t3;
    int *p_cnt, *p_rowstart, *p_csr_src;
    float4 *p_gA;
    float2 *p_gB;
    cudaGetSymbolAddress((void**)&p_in8, g_in8);
    cudaGetSymbolAddress((void**)&p_t1, g_t1);
    cudaGetSymbolAddress((void**)&p_t2, g_t2);
    cudaGetSymbolAddress((void**)&p_h, g_h);
    cudaGetSymbolAddress((void**)&p_D, g_D);
    cudaGetSymbolAddress((void**)&p_S, g_S);
    cudaGetSymbolAddress((void**)&p_t3, g_t3);
    cudaGetSymbolAddress((void**)&p_cnt, g_cnt);
    cudaGetSymbolAddress((void**)&p_rowstart, g_rowstart);
    cudaGetSymbolAddress((void**)&p_csr_src, g_csr_src);
    cudaGetSymbolAddress((void**)&p_gA, g_gA);
    cudaGetSymbolAddress((void**)&p_gB, g_gB);

    int* p_deg = p_cnt;
    int* p_cur = p_cnt + NNODES;

    // ---- CSR build ----
    zero_int_kernel<<<(2 * nN + 255) / 256, 256>>>(p_cnt, 2 * nN);
    hist_kernel<<<(nE + 255) / 256, 256>>>(dst, p_deg, nE);
    scan_kernel<<<1, 1024>>>(p_deg, p_rowstart, nN);
    scatter_kernel<<<(nE + 255) / 256, 256>>>(src, dst, elen, p_rowstart, p_cur,
                                              p_csr_src, p_gA, p_gB, nE);

    // ---- embedding MLP ----
    concat_kernel<<<(nN + 255) / 256, 256>>>(x, fs, fn, p_in8, nN);
    gemm2_kernel<8, 128, 2, 16, 8, 1><<<(nN + 15) / 16, 256>>>(p_in8, ew1, eb1, p_t1, nN, 128, 0);
    gemm2_kernel<128, 128, 2, 16, 32, 1><<<(nN + 15) / 16, 256>>>(p_t1, ew2, eb2, p_t2, nN, 128, 0);
    gemm2_kernel<128, 64, 4, 32, 32, 1><<<(nN + 31) / 32, 256>>>(p_t2, ew3, eb3, p_h, nN, 64, 0);

    // ---- 3 CGConv layers ----
    for (int L = 0; L < 3; ++L) {
        const float* wf = (const float*)d_in[11 + 4 * L];
        const float* bf = (const float*)d_in[12 + 4 * L];
        const float* ws = (const float*)d_in[13 + 4 * L];
        const float* bs = (const float*)d_in[14 + 4 * L];
        convproj_kernel<32><<<(nN + 31) / 32, 256>>>(p_h, wf, bf, ws, bs, p_D, p_S, nN);
        edge2_kernel<<<(nN + 7) / 8, 256>>>((const float4*)p_D, (const float4*)p_S, p_h,
                                            p_rowstart, p_csr_src, p_gA, p_gB,
                                            wf + 128 * 64, ws + 128 * 64,
                                            nN, L < 2 ? 1 : 0);
    }

    // ---- readout ----
    gemm2_kernel<64, 64, 4, 32, 64, 2><<<(nN + 31) / 32, 256>>>(p_h, dw1, db1, p_t3, nN, 64, 0);
    desc2_kernel<<<1024, 256>>>(p_t3, dw2, db2, (float*)d_out, nN);
}